// round 6
// baseline (speedup 1.0000x reference)
#include <cuda_runtime.h>

// ---------------------------------------------------------------------------
// Fused Conv2d(1->16,5x5,pad2) + BatchNorm(inference) + ReLU + MaxPool2x2
// Input  x: [128, 1, 224, 224] f32
// Output  : [128, 16, 112, 112] f32
//
// BN is folded into the conv weights/bias by a tiny pre-kernel.
// Main kernel: 1 thread = one pooled 2x2 block (4x4 pre-pool pixels) for all
// 16 output channels. 8x8 input window loaded once into registers, packed
// into f32x2 pairs (even + odd alignment), convolution done with packed
// fma.rn.f32x2 (FFMA2) -> 2x fp32 FMA throughput.
// ---------------------------------------------------------------------------

__device__ float g_wf[16 * 25];  // BN-folded weights
__device__ float g_bf[16];       // BN-folded bias

__global__ void fuse_params_kernel(const float* __restrict__ w,
                                   const float* __restrict__ b,
                                   const float* __restrict__ gamma,
                                   const float* __restrict__ beta,
                                   const float* __restrict__ mean,
                                   const float* __restrict__ var) {
    int c = threadIdx.x;
    if (c < 16) {
        float s = gamma[c] * rsqrtf(var[c] + 1e-5f);
        g_bf[c] = b[c] * s + beta[c] - mean[c] * s;
#pragma unroll
        for (int k = 0; k < 25; k++)
            g_wf[c * 25 + k] = w[c * 25 + k] * s;
    }
}

__device__ __forceinline__ unsigned long long pk2(float lo, float hi) {
    unsigned long long r;
    asm("mov.b64 %0, {%1, %2};" : "=l"(r) : "f"(lo), "f"(hi));
    return r;
}
__device__ __forceinline__ void upk2(unsigned long long v, float& lo, float& hi) {
    asm("mov.b64 {%0, %1}, %2;" : "=f"(lo), "=f"(hi) : "l"(v));
}
__device__ __forceinline__ unsigned long long fma2(unsigned long long a,
                                                   unsigned long long b,
                                                   unsigned long long c) {
    unsigned long long d;
    asm("fma.rn.f32x2 %0, %1, %2, %3;" : "=l"(d) : "l"(a), "l"(b), "l"(c));
    return d;
}

// Grid: 1568 blocks x 256 threads = 401408 threads = 128 images * 56*56 quads.
// Each quad = pooled 2x2 block at (2*qy, 2*qx), i.e. pre-pool rows 4qy..4qy+3.
__global__ __launch_bounds__(256, 1)
void conv_bn_relu_pool_kernel(const float* __restrict__ x,
                              float* __restrict__ out) {
    __shared__ float sw[16 * 25];
    __shared__ float sb[16];
    int t = threadIdx.x;
    for (int i = t; i < 16 * 25; i += 256) sw[i] = g_wf[i];
    if (t < 16) sb[t] = g_bf[t];
    __syncthreads();

    int tid  = blockIdx.x * 256 + t;
    int bimg = tid / 3136;            // 3136 = 56*56 quads per image
    int rem  = tid - bimg * 3136;
    int qy   = rem / 56;
    int qx   = rem - qy * 56;

    const float* xb = x + bimg * (224 * 224);
    int r0 = 4 * qy - 2;   // top row of 8x8 input window (pad=2)
    int c0 = 4 * qx - 2;   // left col

    // --- load 8x8 input window with zero padding (shared by all 16 channels)
    float xin[8][8];
#pragma unroll
    for (int i = 0; i < 8; i++) {
        int r = r0 + i;
        bool rv = ((unsigned)r < 224u);
        const float* xr = xb + r * 224;
#pragma unroll
        for (int j = 0; j < 8; j++) {
            int cc = c0 + j;
            bool v = rv && ((unsigned)cc < 224u);
            xin[i][j] = v ? __ldg(xr + cc) : 0.0f;
        }
    }

    // --- pack pairs: slots 0..3 = even alignment (0,1)(2,3)(4,5)(6,7)
    //                 slots 4..6 = odd alignment  (1,2)(3,4)(5,6)
    unsigned long long P[8][7];
#pragma unroll
    for (int i = 0; i < 8; i++) {
#pragma unroll
        for (int k = 0; k < 4; k++) P[i][k] = pk2(xin[i][2 * k], xin[i][2 * k + 1]);
#pragma unroll
        for (int k = 0; k < 3; k++) P[i][4 + k] = pk2(xin[i][2 * k + 1], xin[i][2 * k + 2]);
    }

    float* ob = out + ((bimg * 16) * 112 + 2 * qy) * 112 + 2 * qx;

#pragma unroll 1
    for (int c = 0; c < 16; c++) {
        const float* wc = sw + c * 25;
        float bf = sb[c];
        unsigned long long bp = pk2(bf, bf);
        unsigned long long acc[4][2];
#pragma unroll
        for (int o = 0; o < 4; o++) { acc[o][0] = bp; acc[o][1] = bp; }

#pragma unroll
        for (int kr = 0; kr < 5; kr++) {
#pragma unroll
            for (int kc = 0; kc < 5; kc++) {
                float w = wc[kr * 5 + kc];
                unsigned long long wp = pk2(w, w);
                // pair slot for output cols (0,1); +1 gives cols (2,3)
                int pi = (kc & 1) ? (4 + (kc >> 1)) : (kc >> 1);
#pragma unroll
                for (int o = 0; o < 4; o++) {
                    acc[o][0] = fma2(P[o + kr][pi],     wp, acc[o][0]);
                    acc[o][1] = fma2(P[o + kr][pi + 1], wp, acc[o][1]);
                }
            }
        }

        // --- ReLU + 2x2 max pool (relu commutes with max)
        float a[4][4];
#pragma unroll
        for (int o = 0; o < 4; o++) {
            upk2(acc[o][0], a[o][0], a[o][1]);
            upk2(acc[o][1], a[o][2], a[o][3]);
        }
        float2 s0, s1;
        s0.x = fmaxf(fmaxf(fmaxf(a[0][0], a[0][1]), fmaxf(a[1][0], a[1][1])), 0.0f);
        s0.y = fmaxf(fmaxf(fmaxf(a[0][2], a[0][3]), fmaxf(a[1][2], a[1][3])), 0.0f);
        s1.x = fmaxf(fmaxf(fmaxf(a[2][0], a[2][1]), fmaxf(a[3][0], a[3][1])), 0.0f);
        s1.y = fmaxf(fmaxf(fmaxf(a[2][2], a[2][3]), fmaxf(a[3][2], a[3][3])), 0.0f);

        *reinterpret_cast<float2*>(ob)       = s0;  // row 2qy
        *reinterpret_cast<float2*>(ob + 112) = s1;  // row 2qy+1
        ob += 112 * 112;                            // next channel plane
    }
}

extern "C" void kernel_launch(void* const* d_in, const int* in_sizes, int n_in,
                              void* d_out, int out_size) {
    const float* x     = (const float*)d_in[0];
    const float* w     = (const float*)d_in[1];
    const float* bias  = (const float*)d_in[2];
    const float* gamma = (const float*)d_in[3];
    const float* beta  = (const float*)d_in[4];
    const float* mean  = (const float*)d_in[5];
    const float* var   = (const float*)d_in[6];
    float* out = (float*)d_out;

    fuse_params_kernel<<<1, 32>>>(w, bias, gamma, beta, mean, var);
    conv_bn_relu_pool_kernel<<<1568, 256>>>(x, out);
}